// round 1
// baseline (speedup 1.0000x reference)
#include <cuda_runtime.h>
#include <math_constants.h>

#define Nn   16384
#define Cc   64
#define KNN  16
#define Rr   4
#define CR   256          // C*R
#define NCHUNK 8
#define CHUNK (Nn / NCHUNK)   // 2048
#define TJ   32           // j-tile
#define RPB  128          // rows (threads) per knn block
#define RI   8            // rows per ag block

// Scratch (device globals; no allocation allowed)
__device__ float g_A[Nn * CR];            // x @ (W1 - W2) + b
__device__ float g_G[Nn * CR];            // x @ W2
__device__ float g_sq[Nn];                // row squared norms
__device__ float g_pd[Nn * NCHUNK * KNN]; // per-chunk top-k distances
__device__ int   g_pi[Nn * NCHUNK * KNN]; // per-chunk top-k indices
__device__ int   g_idx[Nn * KNN];         // final knn indices

// ---------------------------------------------------------------------------
// A/G/sq precompute: block handles RI=8 rows, 256 threads (one output col each)
// ---------------------------------------------------------------------------
__global__ __launch_bounds__(256) void ag_kernel(const float* __restrict__ x,
                                                 const float* __restrict__ W,
                                                 const float* __restrict__ b) {
    __shared__ float shx[RI * Cc];  // 8 x 64
    const int i0  = blockIdx.x * RI;
    const int tid = threadIdx.x;

    shx[tid]       = x[i0 * Cc + tid];
    shx[tid + 256] = x[i0 * Cc + tid + 256];
    __syncthreads();

    if (tid < RI) {
        float s = 0.f;
        #pragma unroll
        for (int c = 0; c < Cc; c++) { float v = shx[tid * Cc + c]; s = fmaf(v, v, s); }
        g_sq[i0 + tid] = s;
    }

    float aacc[RI], gacc[RI];
    const float bb = b[tid];
    #pragma unroll
    for (int r = 0; r < RI; r++) { aacc[r] = bb; gacc[r] = 0.f; }

    #pragma unroll 4
    for (int c = 0; c < Cc; c++) {
        const float w1 = W[c * CR + tid];
        const float w2 = W[(c + Cc) * CR + tid];
        const float wd = w1 - w2;
        #pragma unroll
        for (int r = 0; r < RI; r++) {
            const float xv = shx[r * Cc + c];  // broadcast
            aacc[r] = fmaf(xv, wd, aacc[r]);
            gacc[r] = fmaf(xv, w2, gacc[r]);
        }
    }
    #pragma unroll
    for (int r = 0; r < RI; r++) {
        g_A[(i0 + r) * CR + tid] = aacc[r];
        g_G[(i0 + r) * CR + tid] = gacc[r];
    }
}

// ---------------------------------------------------------------------------
// Streaming top-16 insert into per-thread shared arrays (stride 17 to dodge
// bank conflicts). Keeps current max value/pos in registers.
// ---------------------------------------------------------------------------
__device__ __forceinline__ void topk_insert(float* td, int* ti,
                                            float& dmax, int& mp,
                                            float d, int j) {
    td[mp] = d; ti[mp] = j;
    float m = -CUDART_INF_F; int q = 0;
    #pragma unroll
    for (int p = 0; p < KNN; p++) {
        const float v = td[p];
        if (v > m) { m = v; q = p; }
    }
    dmax = m; mp = q;
}

// ---------------------------------------------------------------------------
// KNN: block = 128 rows (one per thread), blockIdx.y = j-chunk of 2048.
// d(i,j) = sq_i + sq_j - 2 * dot(x_i, x_j). x_i in registers, x_j tile in smem.
// ---------------------------------------------------------------------------
__global__ __launch_bounds__(RPB, 4) void knn_kernel(const float* __restrict__ x) {
    __shared__ float4 shx4[TJ * 16];          // 32 x 64 floats  (8 KB)
    __shared__ float  shsq[TJ];
    __shared__ float  s_td[RPB * 17];
    __shared__ int    s_ti[RPB * 17];

    const int tid   = threadIdx.x;
    const int i     = blockIdx.x * RPB + tid;
    const int chunk = blockIdx.y;
    const float4* __restrict__ x4 = (const float4*)x;

    float xi[Cc];
    #pragma unroll
    for (int c4 = 0; c4 < 16; c4++) {
        const float4 v = x4[i * 16 + c4];
        xi[c4 * 4 + 0] = v.x; xi[c4 * 4 + 1] = v.y;
        xi[c4 * 4 + 2] = v.z; xi[c4 * 4 + 3] = v.w;
    }
    const float sqi = g_sq[i];

    float* td = s_td + tid * 17;
    int*   ti = s_ti + tid * 17;
    #pragma unroll
    for (int p = 0; p < KNN; p++) { td[p] = CUDART_INF_F; ti[p] = -1; }
    float dmax = CUDART_INF_F; int mp = 0;

    const int jbase = chunk * CHUNK;
    for (int t = 0; t < CHUNK / TJ; t++) {
        const int j0 = jbase + t * TJ;
        __syncthreads();
        #pragma unroll
        for (int s = 0; s < (TJ * 16) / RPB; s++) {      // 4 float4 per thread
            const int q = tid + RPB * s;
            shx4[q] = x4[j0 * 16 + q];
        }
        if (tid < TJ) shsq[tid] = g_sq[j0 + tid];
        __syncthreads();

        #pragma unroll
        for (int jj = 0; jj < TJ; jj += 4) {
            float a0 = 0.f, a1 = 0.f, a2 = 0.f, a3 = 0.f;
            #pragma unroll
            for (int c4 = 0; c4 < 16; c4++) {
                const float4 v0 = shx4[(jj + 0) * 16 + c4];
                const float4 v1 = shx4[(jj + 1) * 16 + c4];
                const float4 v2 = shx4[(jj + 2) * 16 + c4];
                const float4 v3 = shx4[(jj + 3) * 16 + c4];
                const float x0 = xi[c4 * 4 + 0], x1 = xi[c4 * 4 + 1];
                const float x2 = xi[c4 * 4 + 2], x3 = xi[c4 * 4 + 3];
                a0 = fmaf(x0, v0.x, a0); a0 = fmaf(x1, v0.y, a0);
                a0 = fmaf(x2, v0.z, a0); a0 = fmaf(x3, v0.w, a0);
                a1 = fmaf(x0, v1.x, a1); a1 = fmaf(x1, v1.y, a1);
                a1 = fmaf(x2, v1.z, a1); a1 = fmaf(x3, v1.w, a1);
                a2 = fmaf(x0, v2.x, a2); a2 = fmaf(x1, v2.y, a2);
                a2 = fmaf(x2, v2.z, a2); a2 = fmaf(x3, v2.w, a2);
                a3 = fmaf(x0, v3.x, a3); a3 = fmaf(x1, v3.y, a3);
                a3 = fmaf(x2, v3.z, a3); a3 = fmaf(x3, v3.w, a3);
            }
            const float d0 = sqi + shsq[jj + 0] - 2.f * a0;
            const float d1 = sqi + shsq[jj + 1] - 2.f * a1;
            const float d2 = sqi + shsq[jj + 2] - 2.f * a2;
            const float d3 = sqi + shsq[jj + 3] - 2.f * a3;
            int j = j0 + jj;
            if (d0 < dmax && j + 0 != i) topk_insert(td, ti, dmax, mp, d0, j + 0);
            if (d1 < dmax && j + 1 != i) topk_insert(td, ti, dmax, mp, d1, j + 1);
            if (d2 < dmax && j + 2 != i) topk_insert(td, ti, dmax, mp, d2, j + 2);
            if (d3 < dmax && j + 3 != i) topk_insert(td, ti, dmax, mp, d3, j + 3);
        }
    }

    #pragma unroll
    for (int p = 0; p < KNN; p++) {
        g_pd[(i * NCHUNK + chunk) * KNN + p] = td[p];
        g_pi[(i * NCHUNK + chunk) * KNN + p] = ti[p];
    }
}

// ---------------------------------------------------------------------------
// Merge 8 x 16 chunk candidates -> final 16 per row. One thread per row.
// ---------------------------------------------------------------------------
__global__ __launch_bounds__(128) void merge_kernel() {
    __shared__ float s_td[128 * 17];
    __shared__ int   s_ti[128 * 17];
    const int tid = threadIdx.x;
    const int i   = blockIdx.x * 128 + tid;

    float* td = s_td + tid * 17;
    int*   ti = s_ti + tid * 17;
    #pragma unroll
    for (int p = 0; p < KNN; p++) { td[p] = CUDART_INF_F; ti[p] = -1; }
    float dmax = CUDART_INF_F; int mp = 0;

    const float* __restrict__ pd = g_pd + i * NCHUNK * KNN;
    const int*   __restrict__ pi = g_pi + i * NCHUNK * KNN;
    for (int q = 0; q < NCHUNK * KNN; q++) {
        const float d = pd[q];
        if (d < dmax) topk_insert(td, ti, dmax, mp, d, pi[q]);
    }
    #pragma unroll
    for (int p = 0; p < KNN; p++) g_idx[i * KNN + p] = ti[p];
}

// ---------------------------------------------------------------------------
// Output: out[i] = relu(max_k (A_i + G_{idx[i,k]})), then (C,R)->(R,C) permute.
// One block per row, 256 threads (one output feature each).
// ---------------------------------------------------------------------------
__global__ __launch_bounds__(CR) void out_kernel(float* __restrict__ out) {
    __shared__ int   sidx[KNN];
    __shared__ float sv[CR];
    const int i = blockIdx.x;
    const int o = threadIdx.x;
    if (o < KNN) sidx[o] = g_idx[i * KNN + o];
    __syncthreads();

    const float a = g_A[i * CR + o];
    float m = -CUDART_INF_F;
    #pragma unroll
    for (int k = 0; k < KNN; k++) {
        m = fmaxf(m, a + g_G[sidx[k] * CR + o]);
    }
    sv[o] = fmaxf(m, 0.f);   // relu commutes with max
    __syncthreads();

    // y[(i*R + r)*C + c] = v[c*R + r];  p = r*C + c
    const int p = o;
    const int r = p >> 6;        // p / 64
    const int c = p & 63;        // p % 64
    out[i * CR + p] = sv[c * Rr + r];
}

// ---------------------------------------------------------------------------
extern "C" void kernel_launch(void* const* d_in, const int* in_sizes, int n_in,
                              void* d_out, int out_size) {
    const float* x = (const float*)d_in[0];
    const float* W = (const float*)d_in[1];
    const float* b = (const float*)d_in[2];
    float* out = (float*)d_out;

    ag_kernel<<<Nn / RI, 256>>>(x, W, b);
    dim3 g(Nn / RPB, NCHUNK);
    knn_kernel<<<g, RPB>>>(x);
    merge_kernel<<<Nn / 128, 128>>>();
    out_kernel<<<Nn, CR>>>(out);
}

// round 3
// speedup vs baseline: 1.3090x; 1.3090x over previous
#include <cuda_runtime.h>
#include <math_constants.h>

#define Nn   16384
#define Cc   64
#define KNN  16
#define Rr   4
#define CR   256              // C*R
#define NCHUNK 8
#define CHUNK (Nn / NCHUNK)   // 2048
#define TILE_J 64             // j-cols per inner tile
#define RI   8                // rows per ag block
#define NLISTS (NCHUNK * 2)   // candidate lists per row

// ---- scratch (device globals; no allocation allowed) ----
__device__ float  g_A[Nn * CR];             // x @ (W1 - W2) + b
__device__ float  g_G[Nn * CR];             // x @ W2
__device__ float  g_sq[Nn];                 // row squared norms
__device__ float4 g_xf[Nn * 32];            // fragment-ordered tf32 hi/lo (8 MB)
__device__ float  g_pd[Nn * NLISTS * KNN];  // per-list top-k distances
__device__ int    g_pi[Nn * NLISTS * KNN];  // per-list top-k indices
__device__ int    g_idx[Nn * KNN];          // final knn indices

// ---------------------------------------------------------------------------
// tf32 helpers
// ---------------------------------------------------------------------------
__device__ __forceinline__ unsigned f2tf32(float v) {
    unsigned r;
    asm("cvt.rna.tf32.f32 %0, %1;" : "=r"(r) : "f"(v));
    return r;
}

__device__ __forceinline__ void mma_tf32(float* c, const unsigned* a,
                                         unsigned b0, unsigned b1) {
    asm volatile(
        "mma.sync.aligned.m16n8k8.row.col.f32.tf32.tf32.f32 "
        "{%0,%1,%2,%3}, {%4,%5,%6,%7}, {%8,%9}, {%0,%1,%2,%3};"
        : "+f"(c[0]), "+f"(c[1]), "+f"(c[2]), "+f"(c[3])
        : "r"(a[0]), "r"(a[1]), "r"(a[2]), "r"(a[3]), "r"(b0), "r"(b1));
}

// ---------------------------------------------------------------------------
// Fragment-order precompute: slot s -> octet o = s>>8, kk = (s>>5)&7,
// lane = s&31 (g = lane>>2, t = lane&3); row j = o*8+g, col c = kk*8+t.
// float4 = (hi(c), lo(c), hi(c+4), lo(c+4)).
// ---------------------------------------------------------------------------
__global__ __launch_bounds__(256) void xf_kernel(const float* __restrict__ x) {
    const int s    = blockIdx.x * 256 + threadIdx.x;   // < Nn*32
    const int lane = s & 31;
    const int kk   = (s >> 5) & 7;
    const int o    = s >> 8;
    const int g = lane >> 2, t = lane & 3;
    const int j = o * 8 + g;
    const int c = kk * 8 + t;

    const float v0 = x[j * Cc + c];
    const float v1 = x[j * Cc + c + 4];
    const unsigned h0 = f2tf32(v0);
    const unsigned h1 = f2tf32(v1);
    const float h0f = __uint_as_float(h0);
    const float h1f = __uint_as_float(h1);
    const unsigned l0 = f2tf32(v0 - h0f);
    const unsigned l1 = f2tf32(v1 - h1f);

    float4 out;
    out.x = h0f;
    out.y = __uint_as_float(l0);
    out.z = h1f;
    out.w = __uint_as_float(l1);
    g_xf[s] = out;
}

// ---------------------------------------------------------------------------
// A/G/sq precompute (unchanged): block = 8 rows, 256 threads
// ---------------------------------------------------------------------------
__global__ __launch_bounds__(256) void ag_kernel(const float* __restrict__ x,
                                                 const float* __restrict__ W,
                                                 const float* __restrict__ b) {
    __shared__ float shx[RI * Cc];
    const int i0  = blockIdx.x * RI;
    const int tid = threadIdx.x;

    shx[tid]       = x[i0 * Cc + tid];
    shx[tid + 256] = x[i0 * Cc + tid + 256];
    __syncthreads();

    if (tid < RI) {
        float s = 0.f;
        #pragma unroll
        for (int c = 0; c < Cc; c++) { float v = shx[tid * Cc + c]; s = fmaf(v, v, s); }
        g_sq[i0 + tid] = s;
    }

    float aacc[RI], gacc[RI];
    const float bb = b[tid];
    #pragma unroll
    for (int r = 0; r < RI; r++) { aacc[r] = bb; gacc[r] = 0.f; }

    #pragma unroll 4
    for (int c = 0; c < Cc; c++) {
        const float w1 = W[c * CR + tid];
        const float w2 = W[(c + Cc) * CR + tid];
        const float wd = w1 - w2;
        #pragma unroll
        for (int r = 0; r < RI; r++) {
            const float xv = shx[r * Cc + c];
            aacc[r] = fmaf(xv, wd, aacc[r]);
            gacc[r] = fmaf(xv, w2, gacc[r]);
        }
    }
    #pragma unroll
    for (int r = 0; r < RI; r++) {
        g_A[(i0 + r) * CR + tid] = aacc[r];
        g_G[(i0 + r) * CR + tid] = gacc[r];
    }
}

// ---------------------------------------------------------------------------
// Streaming top-16 insert (per-thread smem lists, stride 17 = conflict-free)
// ---------------------------------------------------------------------------
__device__ __forceinline__ void topk_insert(float* td, int* ti,
                                            float& dmax, int& mp,
                                            float d, int j) {
    td[mp] = d; ti[mp] = j;
    float m = -CUDART_INF_F; int q = 0;
    #pragma unroll
    for (int p = 0; p < KNN; p++) {
        const float v = td[p];
        if (v > m) { m = v; q = p; }
    }
    dmax = m; mp = q;
}

// ---------------------------------------------------------------------------
// KNN via tf32x3 tensor-core GEMM.
// CTA: 128 i-rows x 2048 j-chunk. 8 warps, M=16 rows/warp, j-tiles of 64.
// ---------------------------------------------------------------------------
#define SP 73                                    // padded sS stride (floats)
#define SMEM_B    0
#define SMEM_S    32768                          // 2048 float4 for B
#define SMEM_TD   (SMEM_S  + 128 * SP * 4)       // sS: 128 x 73 floats
#define SMEM_TI   (SMEM_TD + 256 * 17 * 4)
#define SMEM_SQJ  (SMEM_TI + 256 * 17 * 4)
#define SMEM_TOT  (SMEM_SQJ + TILE_J * 4)        // = 105,472-ish

__global__ __launch_bounds__(256, 2) void knn_mma_kernel() {
    extern __shared__ char smem[];
    float4* sB4  = (float4*)(smem + SMEM_B);
    float*  sS   = (float*) (smem + SMEM_S);
    float*  std_ = (float*) (smem + SMEM_TD);
    int*    sti  = (int*)   (smem + SMEM_TI);
    float*  ssqj = (float*) (smem + SMEM_SQJ);

    const int tid   = threadIdx.x;
    const int lane  = tid & 31;
    const int w     = tid >> 5;
    const int g     = lane >> 2;
    const int t     = lane & 3;
    const int i0    = blockIdx.x * 128;
    const int chunk = blockIdx.y;

    // ---- A fragments for rows [i0 + w*16, i0 + w*16 + 16), K = 64 ----
    unsigned Ahi[32], Alo[32];
    {
        const int oA0 = (i0 + w * 16) >> 3;
        #pragma unroll
        for (int kk = 0; kk < 8; kk++) {
            const float4 fa = g_xf[(oA0 * 8 + kk) * 32 + lane];        // rows g   -> a0,a2
            const float4 fb = g_xf[((oA0 + 1) * 8 + kk) * 32 + lane];  // rows g+8 -> a1,a3
            Ahi[kk * 4 + 0] = __float_as_uint(fa.x); Alo[kk * 4 + 0] = __float_as_uint(fa.y);
            Ahi[kk * 4 + 2] = __float_as_uint(fa.z); Alo[kk * 4 + 2] = __float_as_uint(fa.w);
            Ahi[kk * 4 + 1] = __float_as_uint(fb.x); Alo[kk * 4 + 1] = __float_as_uint(fb.y);
            Ahi[kk * 4 + 3] = __float_as_uint(fb.z); Alo[kk * 4 + 3] = __float_as_uint(fb.w);
        }
    }

    // ---- scan role: thread t handles row tid>>1, half tid&1 (32 cols) ----
    const int   srow  = tid >> 1;
    const int   shalf = tid & 1;
    const int   ig    = i0 + srow;
    const float sqi   = g_sq[ig];

    float* td = std_ + tid * 17;
    int*   ti = sti  + tid * 17;
    #pragma unroll
    for (int p = 0; p < KNN; p++) { td[p] = CUDART_INF_F; ti[p] = -1; }
    float dmax = CUDART_INF_F; int mp = 0;

    for (int tt = 0; tt < CHUNK / TILE_J; tt++) {
        const int j0 = chunk * CHUNK + tt * TILE_J;

        __syncthreads();  // previous iter's mma/scan done before refill
        {
            const float4* __restrict__ src = g_xf + (j0 >> 3) * 256;
            #pragma unroll
            for (int s = 0; s < 8; s++) sB4[tid + 256 * s] = src[tid + 256 * s];
            if (tid < TILE_J) ssqj[tid] = g_sq[j0 + tid];
        }
        __syncthreads();

        // ---- GEMM: S[128 x 64] = Xi . Xj^T via tf32x3 ----
        #pragma unroll
        for (int ntp = 0; ntp < 4; ntp++) {
            float c0[4] = {0.f, 0.f, 0.f, 0.f};
            float c1[4] = {0.f, 0.f, 0.f, 0.f};
            #pragma unroll
            for (int kk = 0; kk < 8; kk++) {
                const float4 bv0 = sB4[((2 * ntp + 0) * 8 + kk) * 32 + lane];
                const float4 bv1 = sB4[((2 * ntp + 1) * 8 + kk) * 32 + lane];
                const unsigned b0h = __float_as_uint(bv0.x), b0l = __float_as_uint(bv0.y);
                const unsigned b2h = __float_as_uint(bv0.z), b2l = __float_as_uint(bv0.w);
                const unsigned b1h = __float_as_uint(bv1.x), b1l = __float_as_uint(bv1.y);
                const unsigned b3h = __float_as_uint(bv1.z), b3l = __float_as_uint(bv1.w);
                mma_tf32(c0, Ahi + kk * 4, b0h, b2h);   // hi . hi
                mma_tf32(c1, Ahi + kk * 4, b1h, b3h);
                mma_tf32(c0, Alo + kk * 4, b0h, b2h);   // lo . hi
                mma_tf32(c1, Alo + kk * 4, b1h, b3h);
                mma_tf32(c0, Ahi + kk * 4, b0l, b2l);   // hi . lo
                mma_tf32(c1, Ahi + kk * 4, b1l, b3l);
            }
            const int r0 = w * 16 + g;
            const int ca = (2 * ntp + 0) * 8 + 2 * t;
            const int cb = (2 * ntp + 1) * 8 + 2 * t;
            sS[r0 * SP + ca]           = c0[0];
            sS[r0 * SP + ca + 1]       = c0[1];
            sS[(r0 + 8) * SP + ca]     = c0[2];
            sS[(r0 + 8) * SP + ca + 1] = c0[3];
            sS[r0 * SP + cb]           = c1[0];
            sS[r0 * SP + cb + 1]       = c1[1];
            sS[(r0 + 8) * SP + cb]     = c1[2];
            sS[(r0 + 8) * SP + cb + 1] = c1[3];
        }
        __syncthreads();

        // ---- scan: distances + streaming top-16 ----
        const float* srowS = sS + srow * SP + shalf * 32;
        const float* sqjp  = ssqj + shalf * 32;
        const int    jb    = j0 + shalf * 32;
        #pragma unroll 8
        for (int c = 0; c < 32; c++) {
            const float d = sqi + sqjp[c] - 2.f * srowS[c];
            const int   jg = jb + c;
            if (d < dmax && jg != ig) topk_insert(td, ti, dmax, mp, d, jg);
        }
    }

    // ---- write candidate list ----
    const int li = ig * NLISTS + chunk * 2 + shalf;
    #pragma unroll
    for (int p = 0; p < KNN; p++) {
        g_pd[li * KNN + p] = td[p];
        g_pi[li * KNN + p] = ti[p];
    }
}

// ---------------------------------------------------------------------------
// Merge 16 lists x 16 -> final 16 per row. One thread per row.
// ---------------------------------------------------------------------------
__global__ __launch_bounds__(128) void merge_kernel() {
    __shared__ float s_td[128 * 17];
    __shared__ int   s_ti[128 * 17];
    const int tid = threadIdx.x;
    const int i   = blockIdx.x * 128 + tid;

    float* td = s_td + tid * 17;
    int*   ti = s_ti + tid * 17;
    #pragma unroll
    for (int p = 0; p < KNN; p++) { td[p] = CUDART_INF_F; ti[p] = -1; }
    float dmax = CUDART_INF_F; int mp = 0;

    const float* __restrict__ pd = g_pd + i * NLISTS * KNN;
    const int*   __restrict__ pi = g_pi + i * NLISTS * KNN;
    for (int q = 0; q < NLISTS * KNN; q++) {
        const float d = pd[q];
        if (d < dmax) topk_insert(td, ti, dmax, mp, d, pi[q]);
    }
    #pragma unroll
    for (int p = 0; p < KNN; p++) g_idx[i * KNN + p] = ti[p];
}

// ---------------------------------------------------------------------------
// Output: out[i] = relu(max_k (A_i + G_{idx[i,k]})), then (C,R)->(R,C) permute
// ---------------------------------------------------------------------------
__global__ __launch_bounds__(CR) void out_kernel(float* __restrict__ out) {
    __shared__ int   sidx[KNN];
    __shared__ float sv[CR];
    const int i = blockIdx.x;
    const int o = threadIdx.x;
    if (o < KNN) sidx[o] = g_idx[i * KNN + o];
    __syncthreads();

    const float a = g_A[i * CR + o];
    float m = -CUDART_INF_F;
    #pragma unroll
    for (int k = 0; k < KNN; k++) {
        m = fmaxf(m, a + g_G[sidx[k] * CR + o]);
    }
    sv[o] = fmaxf(m, 0.f);
    __syncthreads();

    const int p = o;
    const int r = p >> 6;
    const int c = p & 63;
    out[i * CR + p] = sv[c * Rr + r];
}

// ---------------------------------------------------------------------------
extern "C" void kernel_launch(void* const* d_in, const int* in_sizes, int n_in,
                              void* d_out, int out_size) {
    const float* x = (const float*)d_in[0];
    const float* W = (const float*)d_in[1];
    const float* b = (const float*)d_in[2];
    float* out = (float*)d_out;

    cudaFuncSetAttribute(knn_mma_kernel,
                         cudaFuncAttributeMaxDynamicSharedMemorySize, SMEM_TOT);

    xf_kernel<<<Nn * 32 / 256, 256>>>(x);
    ag_kernel<<<Nn / RI, 256>>>(x, W, b);
    dim3 g(Nn / 128, NCHUNK);
    knn_mma_kernel<<<g, 256, SMEM_TOT>>>();
    merge_kernel<<<Nn / 128, 128>>>();
    out_kernel<<<Nn, CR>>>(out);
}

// round 7
// speedup vs baseline: 1.3797x; 1.0540x over previous
#include <cuda_runtime.h>
#include <math_constants.h>
#include <cstdint>

#define Nn   16384
#define Cc   64
#define KNN  16
#define Rr   4
#define CR   256              // C*R
#define RI   8                // rows per ag block
#define IB   128              // i-rows per knn CTA
#define TJ   64               // j-tile
#define NT   (Nn / TJ)        // 256 tiles

// ---- scratch (device globals; no allocation allowed) ----
__device__ float  g_A[Nn * CR];     // x @ (W1 - W2) + b
__device__ float  g_G[Nn * CR];     // x @ W2
__device__ float  g_sq[Nn];         // row squared norms
__device__ float4 g_xf[Nn * 32];    // fragment-ordered tf32 hi/lo (8 MB)
__device__ int    g_idx[Nn * KNN];  // final knn indices

// ---- smem map (bytes) for knn kernel ----
#define SM_B    0                        // 2 x 2048 float4 = 65536
#define SM_SQJ  65536                    // 2 x 64 floats = 512
#define SM_TD0  66048                    // 256*17 floats
#define SM_TI0  83456
#define SM_TD1  100864
#define SM_TI1  118272
#define SM_TOT  135680

__device__ __forceinline__ uint32_t smem_u32(const void* p) {
    uint32_t a;
    asm("{ .reg .u64 t; cvta.to.shared.u64 t, %1; cvt.u32.u64 %0, t; }" : "=r"(a) : "l"(p));
    return a;
}

__device__ __forceinline__ unsigned f2tf32(float v) {
    unsigned r;
    asm("cvt.rna.tf32.f32 %0, %1;" : "=r"(r) : "f"(v));
    return r;
}

__device__ __forceinline__ void mma_tf32(float* c, const uint32_t* a,
                                         float b0, float b1) {
    asm volatile(
        "mma.sync.aligned.m16n8k8.row.col.f32.tf32.tf32.f32 "
        "{%0,%1,%2,%3}, {%4,%5,%6,%7}, {%8,%9}, {%0,%1,%2,%3};"
        : "+f"(c[0]), "+f"(c[1]), "+f"(c[2]), "+f"(c[3])
        : "r"(a[0]), "r"(a[1]), "r"(a[2]), "r"(a[3]),
          "r"(__float_as_uint(b0)), "r"(__float_as_uint(b1)));
}

__device__ __forceinline__ void cpa16(uint32_t dst, const void* src) {
    asm volatile("cp.async.cg.shared.global [%0], [%1], 16;"
                 :: "r"(dst), "l"(__cvta_generic_to_global(src)));
}
__device__ __forceinline__ void cpa4(uint32_t dst, const void* src) {
    asm volatile("cp.async.ca.shared.global [%0], [%1], 4;"
                 :: "r"(dst), "l"(__cvta_generic_to_global(src)));
}

// ---------------------------------------------------------------------------
// Fragment-order precompute (validated in R3): slot s -> octet o = s>>8,
// kk = (s>>5)&7, lane = s&31 (g = lane>>2, t = lane&3); row j = o*8+g,
// col c = kk*8+t. float4 = (hi(c), lo(c), hi(c+4), lo(c+4)).
// Serves as both A-row and B-col fragments of m16n8k8.row.col.
// ---------------------------------------------------------------------------
__global__ __launch_bounds__(256) void xf_kernel(const float* __restrict__ x) {
    const int s    = blockIdx.x * 256 + threadIdx.x;   // < Nn*32
    const int lane = s & 31;
    const int kk   = (s >> 5) & 7;
    const int o    = s >> 8;
    const int g = lane >> 2, t = lane & 3;
    const int j = o * 8 + g;
    const int c = kk * 8 + t;

    const float v0 = x[j * Cc + c];
    const float v1 = x[j * Cc + c + 4];
    const unsigned h0 = f2tf32(v0);
    const unsigned h1 = f2tf32(v1);
    const float h0f = __uint_as_float(h0);
    const float h1f = __uint_as_float(h1);
    const unsigned l0 = f2tf32(v0 - h0f);
    const unsigned l1 = f2tf32(v1 - h1f);

    float4 out;
    out.x = h0f;
    out.y = __uint_as_float(l0);
    out.z = h1f;
    out.w = __uint_as_float(l1);
    g_xf[s] = out;
}

// ---------------------------------------------------------------------------
// A/G/sq precompute: block = 8 rows, 256 threads
// ---------------------------------------------------------------------------
__global__ __launch_bounds__(256) void ag_kernel(const float* __restrict__ x,
                                                 const float* __restrict__ W,
                                                 const float* __restrict__ b) {
    __shared__ float shx[RI * Cc];
    const int i0  = blockIdx.x * RI;
    const int tid = threadIdx.x;

    shx[tid]       = x[i0 * Cc + tid];
    shx[tid + 256] = x[i0 * Cc + tid + 256];
    __syncthreads();

    if (tid < RI) {
        float s = 0.f;
        #pragma unroll
        for (int c = 0; c < Cc; c++) { float v = shx[tid * Cc + c]; s = fmaf(v, v, s); }
        g_sq[i0 + tid] = s;
    }

    float aacc[RI], gacc[RI];
    const float bb = b[tid];
    #pragma unroll
    for (int r = 0; r < RI; r++) { aacc[r] = bb; gacc[r] = 0.f; }

    #pragma unroll 4
    for (int c = 0; c < Cc; c++) {
        const float w1 = W[c * CR + tid];
        const float w2 = W[(c + Cc) * CR + tid];
        const float wd = w1 - w2;
        #pragma unroll
        for (int r = 0; r < RI; r++) {
            const float xv = shx[r * Cc + c];
            aacc[r] = fmaf(xv, wd, aacc[r]);
            gacc[r] = fmaf(xv, w2, gacc[r]);
        }
    }
    #pragma unroll
    for (int r = 0; r < RI; r++) {
        g_A[(i0 + r) * CR + tid] = aacc[r];
        g_G[(i0 + r) * CR + tid] = gacc[r];
    }
}

// ---------------------------------------------------------------------------
// Streaming top-16 insert (per-thread smem lists, stride 17 = conflict-free)
// ---------------------------------------------------------------------------
__device__ __forceinline__ void topk_insert(float* td, int* ti,
                                            float& dmax, int& mp,
                                            float d, int j) {
    td[mp] = d; ti[mp] = j;
    float m = -CUDART_INF_F; int q = 0;
    #pragma unroll
    for (int p = 0; p < KNN; p++) {
        const float v = td[p];
        if (v > m) { m = v; q = p; }
    }
    dmax = m; mp = q;
}

// ---------------------------------------------------------------------------
// KNN via tf32x3 mma.sync, register epilogue, double-buffered cp.async B.
// CTA = 128 i-rows (8 warps x 16 rows), sweeps all j in tiles of 64.
// Thread (g,t) of warp w: rows (w*16+g, +8); per n-octet handles cols 2t,2t+1.
// Ranking metric: sq_j - 2*dot (sq_i constant per row, dropped).
// ---------------------------------------------------------------------------
__global__ __launch_bounds__(256, 1) void knn_tf32_kernel() {
    extern __shared__ char smem[];
    const uint32_t sb  = smem_u32(smem);
    const float4* sB   = (const float4*)smem;             // [2][2048]
    const float*  sqjs = (const float*)(smem + SM_SQJ);   // [2][64]

    const int tid  = threadIdx.x;
    const int w    = tid >> 5;
    const int lane = tid & 31;
    const int g_   = lane >> 2;
    const int t_   = lane & 3;
    const int bid  = blockIdx.x;
    const int i0   = bid * IB;
    const int ig0  = i0 + w * 16 + g_;
    const int ig1  = ig0 + 8;

    // ---- A fragments: rows i0 + w*16 .. +15 = octets oA, oA+1 ----
    uint32_t Ah[32], Al[32];   // [kk][4]
    {
        const int oA = bid * 16 + w * 2;
        #pragma unroll
        for (int kk = 0; kk < 8; kk++) {
            const float4 fa = g_xf[(oA * 8 + kk) * 32 + lane];        // rows g   -> a0,a2
            const float4 fb = g_xf[((oA + 1) * 8 + kk) * 32 + lane];  // rows g+8 -> a1,a3
            Ah[kk * 4 + 0] = __float_as_uint(fa.x); Al[kk * 4 + 0] = __float_as_uint(fa.y);
            Ah[kk * 4 + 1] = __float_as_uint(fb.x); Al[kk * 4 + 1] = __float_as_uint(fb.y);
            Ah[kk * 4 + 2] = __float_as_uint(fa.z); Al[kk * 4 + 2] = __float_as_uint(fa.w);
            Ah[kk * 4 + 3] = __float_as_uint(fb.z); Al[kk * 4 + 3] = __float_as_uint(fb.w);
        }
    }

    // ---- per-thread top-16 lists (row g_, row g_+8) ----
    float* td0 = (float*)(smem + SM_TD0) + tid * 17;
    int*   ti0 = (int*)  (smem + SM_TI0) + tid * 17;
    float* td1 = (float*)(smem + SM_TD1) + tid * 17;
    int*   ti1 = (int*)  (smem + SM_TI1) + tid * 17;
    #pragma unroll
    for (int p = 0; p < KNN; p++) {
        td0[p] = CUDART_INF_F; ti0[p] = -1;
        td1[p] = CUDART_INF_F; ti1[p] = -1;
    }
    float dmax0 = CUDART_INF_F, dmax1 = CUDART_INF_F;
    int   mp0 = 0, mp1 = 0;

    // ---- tile fill: tile jt -> buffer buf (2048 float4 + 64 sq) ----
    auto fill = [&](int jt, int buf) {
        const uint32_t dstB = sb + SM_B + buf * 32768 + tid * 16;
        const float4* src = g_xf + (size_t)jt * 2048 + tid;
        #pragma unroll
        for (int s = 0; s < 8; s++) cpa16(dstB + s * 4096, src + s * 256);
        if (tid < TJ) cpa4(sb + SM_SQJ + buf * 256 + tid * 4, &g_sq[jt * TJ + tid]);
    };

    fill(0, 0);
    asm volatile("cp.async.commit_group;" ::: "memory");
    asm volatile("cp.async.wait_group 0;" ::: "memory");
    __syncthreads();

    for (int tt = 0; tt < NT; tt++) {
        const int buf = tt & 1;
        if (tt + 1 < NT) {
            fill(tt + 1, buf ^ 1);
            asm volatile("cp.async.commit_group;" ::: "memory");
        }
        const float4* Bb  = sB + buf * 2048;
        const float*  sqj = sqjs + buf * TJ;
        const int jbase   = tt * TJ;

        #pragma unroll 2
        for (int ob = 0; ob < 8; ob++) {
            float ch[4] = {0.f, 0.f, 0.f, 0.f};
            float cl[4] = {0.f, 0.f, 0.f, 0.f};
            #pragma unroll
            for (int kk = 0; kk < 8; kk++) {
                const float4 bv = Bb[(ob * 8 + kk) * 32 + lane];
                mma_tf32(ch, Ah + kk * 4, bv.x, bv.z);   // hi . hi
                mma_tf32(cl, Al + kk * 4, bv.x, bv.z);   // lo . hi
                mma_tf32(cl, Ah + kk * 4, bv.y, bv.w);   // hi . lo
            }
            const int   jl = ob * 8 + 2 * t_;
            const float s0 = sqj[jl], s1 = sqj[jl + 1];
            const float d00 = s0 - 2.f * (ch[0] + cl[0]);   // row g_,   col jl
            const float d01 = s1 - 2.f * (ch[1] + cl[1]);   // row g_,   col jl+1
            const float d10 = s0 - 2.f * (ch[2] + cl[2]);   // row g_+8, col jl
            const float d11 = s1 - 2.f * (ch[3] + cl[3]);   // row g_+8, col jl+1
            const int jg = jbase + jl;
            if (d00 < dmax0 && jg     != ig0) topk_insert(td0, ti0, dmax0, mp0, d00, jg);
            if (d01 < dmax0 && jg + 1 != ig0) topk_insert(td0, ti0, dmax0, mp0, d01, jg + 1);
            if (d10 < dmax1 && jg     != ig1) topk_insert(td1, ti1, dmax1, mp1, d10, jg);
            if (d11 < dmax1 && jg + 1 != ig1) topk_insert(td1, ti1, dmax1, mp1, d11, jg + 1);
        }

        asm volatile("cp.async.wait_group 0;" ::: "memory");
        __syncthreads();
    }

    // ---- merge the 4 col-stripe lists per row (t_ == 0 does it) ----
    __syncthreads();
    if (t_ == 0) {
        #pragma unroll
        for (int s = 1; s < 4; s++) {
            const float* od0 = (const float*)(smem + SM_TD0) + (tid + s) * 17;
            const int*   oi0 = (const int*)  (smem + SM_TI0) + (tid + s) * 17;
            const float* od1 = (const float*)(smem + SM_TD1) + (tid + s) * 17;
            const int*   oi1 = (const int*)  (smem + SM_TI1) + (tid + s) * 17;
            #pragma unroll
            for (int p = 0; p < KNN; p++) {
                const float a = od0[p];
                if (a < dmax0) topk_insert(td0, ti0, dmax0, mp0, a, oi0[p]);
                const float c = od1[p];
                if (c < dmax1) topk_insert(td1, ti1, dmax1, mp1, c, oi1[p]);
            }
        }
        #pragma unroll
        for (int p = 0; p < KNN; p++) {
            g_idx[ig0 * KNN + p] = ti0[p];
            g_idx[ig1 * KNN + p] = ti1[p];
        }
    }
}

// ---------------------------------------------------------------------------
// Output: out[i] = relu(max_k (A_i + G_{idx[i,k]})), then (C,R)->(R,C) permute
// ---------------------------------------------------------------------------
__global__ __launch_bounds__(CR) void out_kernel(float* __restrict__ out) {
    __shared__ int   sidx[KNN];
    __shared__ float sv[CR];
    const int i = blockIdx.x;
    const int o = threadIdx.x;
    if (o < KNN) sidx[o] = g_idx[i * KNN + o];
    __syncthreads();

    const float a = g_A[i * CR + o];
    float m = -CUDART_INF_F;
    #pragma unroll
    for (int k = 0; k < KNN; k++) {
        m = fmaxf(m, a + g_G[sidx[k] * CR + o]);
    }
    sv[o] = fmaxf(m, 0.f);
    __syncthreads();

    const int p = o;
    const int r = p >> 6;
    const int c = p & 63;
    out[i * CR + p] = sv[c * Rr + r];
}

// ---------------------------------------------------------------------------
extern "C" void kernel_launch(void* const* d_in, const int* in_sizes, int n_in,
                              void* d_out, int out_size) {
    const float* x = (const float*)d_in[0];
    const float* W = (const float*)d_in[1];
    const float* b = (const float*)d_in[2];
    float* out = (float*)d_out;

    cudaFuncSetAttribute(knn_tf32_kernel,
                         cudaFuncAttributeMaxDynamicSharedMemorySize, SM_TOT);

    xf_kernel<<<Nn * 32 / 256, 256>>>(x);
    ag_kernel<<<Nn / RI, 256>>>(x, W, b);
    knn_tf32_kernel<<<Nn / IB, 256, SM_TOT>>>();
    out_kernel<<<Nn, CR>>>(out);
}

// round 8
// speedup vs baseline: 2.0273x; 1.4693x over previous
#include <cuda_runtime.h>
#include <cuda_fp16.h>
#include <math_constants.h>
#include <cstdint>

#define Nn   16384
#define Cc   64
#define KNN  16
#define Rr   4
#define CR   256              // C*R
#define RI   8                // rows per ag block
#define IB   128              // i-rows per knn CTA
#define TJ   128              // j-tile
#define NT   (Nn / TJ)        // 128 tiles
#define LOSCALE 2048.0f       // lo-plane pre-scale (exact power of 2)
#define LOINV (1.0f / 2048.0f)

// ---- scratch (device globals; no allocation allowed) ----
__device__ float g_A[Nn * CR];       // x @ (W1 - W2) + b
__device__ float g_G[Nn * CR];       // x @ W2
__device__ float g_sq[Nn];           // row squared norms
__device__ uint4 g_xp[Nn * 16];      // fp16 hi/lo fragment-packed (4 MB)
__device__ int   g_idx[Nn * KNN];    // final knn indices

// ---- smem map (bytes) for knn kernel ----
#define SM_B    0                         // 2 x 2048 uint4 = 65536
#define SM_SQJ  65536                     // 2 x 128 floats = 1024
#define SM_TD0  66560                     // 256*17 floats
#define SM_TI0  83968
#define SM_TD1  101376
#define SM_TI1  118784
#define SM_TOT  136192

__device__ __forceinline__ uint32_t smem_u32(const void* p) {
    uint32_t a;
    asm("{ .reg .u64 t; cvta.to.shared.u64 t, %1; cvt.u32.u64 %0, t; }" : "=r"(a) : "l"(p));
    return a;
}

__device__ __forceinline__ void mma_f16(float* c, const uint32_t* a,
                                        uint32_t b0, uint32_t b1) {
    asm volatile(
        "mma.sync.aligned.m16n8k16.row.col.f32.f16.f16.f32 "
        "{%0,%1,%2,%3}, {%4,%5,%6,%7}, {%8,%9}, {%0,%1,%2,%3};"
        : "+f"(c[0]), "+f"(c[1]), "+f"(c[2]), "+f"(c[3])
        : "r"(a[0]), "r"(a[1]), "r"(a[2]), "r"(a[3]), "r"(b0), "r"(b1));
}

__device__ __forceinline__ void cpa16(uint32_t dst, const void* src) {
    asm volatile("cp.async.cg.shared.global [%0], [%1], 16;"
                 :: "r"(dst), "l"(__cvta_generic_to_global(src)));
}
__device__ __forceinline__ void cpa4(uint32_t dst, const void* src) {
    asm volatile("cp.async.ca.shared.global [%0], [%1], 4;"
                 :: "r"(dst), "l"(__cvta_generic_to_global(src)));
}

__device__ __forceinline__ uint32_t pack_h2(float a, float b) {  // a in low half
    __half2 h = __floats2half2_rn(a, b);
    return reinterpret_cast<uint32_t&>(h);
}

// ---------------------------------------------------------------------------
// Fragment pack (mapping validated in R5): slot s -> octet o = s>>7,
// q = (s>>5)&3, lane = s&31 (g = lane>>2, t = lane&3); row j = o*8+g,
// cols c = q*16 + 2t (+1, +8, +9).
// uint4 = (w0hi, w1hi, w0lo, w1lo); w0 = cols (2t,2t+1), w1 = cols (2t+8,2t+9).
// lo plane pre-scaled by 2048 to stay in fp16 normal range.
// Serves as both A-row and B-col fragments of m16n8k16.row.col.
// ---------------------------------------------------------------------------
__global__ __launch_bounds__(256) void xf_kernel(const float* __restrict__ x) {
    const int s    = blockIdx.x * 256 + threadIdx.x;  // < Nn*16
    const int lane = s & 31;
    const int q    = (s >> 5) & 3;
    const int o    = s >> 7;
    const int g = lane >> 2, t = lane & 3;
    const int j = o * 8 + g;
    const int c = q * 16 + 2 * t;

    const float v0 = x[j * Cc + c];
    const float v1 = x[j * Cc + c + 1];
    const float v2 = x[j * Cc + c + 8];
    const float v3 = x[j * Cc + c + 9];

    const float h0 = __half2float(__float2half_rn(v0));
    const float h1 = __half2float(__float2half_rn(v1));
    const float h2 = __half2float(__float2half_rn(v2));
    const float h3 = __half2float(__float2half_rn(v3));

    uint4 out;
    out.x = pack_h2(h0, h1);
    out.y = pack_h2(h2, h3);
    out.z = pack_h2((v0 - h0) * LOSCALE, (v1 - h1) * LOSCALE);
    out.w = pack_h2((v2 - h2) * LOSCALE, (v3 - h3) * LOSCALE);
    g_xp[s] = out;
}

// ---------------------------------------------------------------------------
// A/G/sq precompute: block = 8 rows, 256 threads
// ---------------------------------------------------------------------------
__global__ __launch_bounds__(256) void ag_kernel(const float* __restrict__ x,
                                                 const float* __restrict__ W,
                                                 const float* __restrict__ b) {
    __shared__ float shx[RI * Cc];
    const int i0  = blockIdx.x * RI;
    const int tid = threadIdx.x;

    shx[tid]       = x[i0 * Cc + tid];
    shx[tid + 256] = x[i0 * Cc + tid + 256];
    __syncthreads();

    if (tid < RI) {
        float s = 0.f;
        #pragma unroll
        for (int c = 0; c < Cc; c++) { float v = shx[tid * Cc + c]; s = fmaf(v, v, s); }
        g_sq[i0 + tid] = s;
    }

    float aacc[RI], gacc[RI];
    const float bb = b[tid];
    #pragma unroll
    for (int r = 0; r < RI; r++) { aacc[r] = bb; gacc[r] = 0.f; }

    #pragma unroll 4
    for (int c = 0; c < Cc; c++) {
        const float w1 = W[c * CR + tid];
        const float w2 = W[(c + Cc) * CR + tid];
        const float wd = w1 - w2;
        #pragma unroll
        for (int r = 0; r < RI; r++) {
            const float xv = shx[r * Cc + c];
            aacc[r] = fmaf(xv, wd, aacc[r]);
            gacc[r] = fmaf(xv, w2, gacc[r]);
        }
    }
    #pragma unroll
    for (int r = 0; r < RI; r++) {
        g_A[(i0 + r) * CR + tid] = aacc[r];
        g_G[(i0 + r) * CR + tid] = gacc[r];
    }
}

// ---------------------------------------------------------------------------
// Streaming top-16 insert (per-thread smem lists, stride 17 = conflict-free)
// ---------------------------------------------------------------------------
__device__ __forceinline__ void topk_insert(float* td, int* ti,
                                            float& dmax, int& mp,
                                            float d, int j) {
    td[mp] = d; ti[mp] = j;
    float m = -CUDART_INF_F; int q = 0;
    #pragma unroll
    for (int p = 0; p < KNN; p++) {
        const float v = td[p];
        if (v > m) { m = v; q = p; }
    }
    dmax = m; mp = q;
}

// ---------------------------------------------------------------------------
// KNN via fp16x3 mma.sync (m16n8k16), register epilogue, double-buffered
// cp.async B. CTA = 128 i-rows (8 warps x 16 rows), tiles of 128 j.
// Thread (g,t) of warp w: rows (w*16+g, +8); per n-octet cols 2t,2t+1.
// Ranking metric: sq_j - 2*dot (sq_i constant per row, dropped).
// dot = ch + (cl + cl2) / 2048  (cross terms carry the lo pre-scale).
// ---------------------------------------------------------------------------
__global__ __launch_bounds__(256, 1) void knn_f16_kernel() {
    extern __shared__ char smem[];
    const uint32_t sb  = smem_u32(smem);
    const uint4* sB    = (const uint4*)smem;             // [2][2048]
    const float* sqjs  = (const float*)(smem + SM_SQJ);  // [2][128]

    const int tid  = threadIdx.x;
    const int w    = tid >> 5;
    const int lane = tid & 31;
    const int g_   = lane >> 2;
    const int t_   = lane & 3;
    const int bid  = blockIdx.x;
    const int i0   = bid * IB;
    const int ig0  = i0 + w * 16 + g_;
    const int ig1  = ig0 + 8;

    // ---- A fragments: rows i0 + w*16 .. +15 = octets oA, oA+1 ----
    uint32_t Ah[16], Al[16];   // [q][4]
    {
        const int oA = bid * 16 + w * 2;
        #pragma unroll
        for (int q = 0; q < 4; q++) {
            const uint4 ua = g_xp[(oA * 4 + q) * 32 + lane];
            const uint4 ub = g_xp[((oA + 1) * 4 + q) * 32 + lane];
            Ah[q * 4 + 0] = ua.x; Ah[q * 4 + 1] = ub.x;
            Ah[q * 4 + 2] = ua.y; Ah[q * 4 + 3] = ub.y;
            Al[q * 4 + 0] = ua.z; Al[q * 4 + 1] = ub.z;
            Al[q * 4 + 2] = ua.w; Al[q * 4 + 3] = ub.w;
        }
    }

    // ---- per-thread top-16 lists (row g_, row g_+8) ----
    float* td0 = (float*)(smem + SM_TD0) + tid * 17;
    int*   ti0 = (int*)  (smem + SM_TI0) + tid * 17;
    float* td1 = (float*)(smem + SM_TD1) + tid * 17;
    int*   ti1 = (int*)  (smem + SM_TI1) + tid * 17;
    #pragma unroll
    for (int p = 0; p < KNN; p++) {
        td0[p] = CUDART_INF_F; ti0[p] = -1;
        td1[p] = CUDART_INF_F; ti1[p] = -1;
    }
    float dmax0 = CUDART_INF_F, dmax1 = CUDART_INF_F;
    int   mp0 = 0, mp1 = 0;

    // ---- tile fill ----
    auto fill = [&](int jt, int buf) {
        const uint32_t dstB = sb + SM_B + buf * 32768 + tid * 16;
        const uint4* src = g_xp + (size_t)jt * 2048 + tid;
        #pragma unroll
        for (int s = 0; s < 8; s++) cpa16(dstB + s * 4096, src + s * 256);
        if (tid < TJ) cpa4(sb + SM_SQJ + buf * 512 + tid * 4, &g_sq[jt * TJ + tid]);
    };

    fill(0, 0);
    asm volatile("cp.async.commit_group;" ::: "memory");
    asm volatile("cp.async.wait_group 0;" ::: "memory");
    __syncthreads();

    for (int tt = 0; tt < NT; tt++) {
        const int buf = tt & 1;
        if (tt + 1 < NT) {
            fill(tt + 1, buf ^ 1);
            asm volatile("cp.async.commit_group;" ::: "memory");
        }
        const uint4* Bb  = sB + buf * 2048;
        const float* sqj = sqjs + buf * TJ;
        const int jbase  = tt * TJ;

        #pragma unroll 2
        for (int ob = 0; ob < 16; ob++) {
            float ch[4]  = {0.f, 0.f, 0.f, 0.f};
            float cl[4]  = {0.f, 0.f, 0.f, 0.f};
            float cl2[4] = {0.f, 0.f, 0.f, 0.f};
            #pragma unroll
            for (int q = 0; q < 4; q++) {
                const uint4 bv = Bb[(ob * 4 + q) * 32 + lane];
                mma_f16(ch,  Ah + q * 4, bv.x, bv.y);   // hi . hi
                mma_f16(cl,  Al + q * 4, bv.x, bv.y);   // lo . hi   (x2048)
                mma_f16(cl2, Ah + q * 4, bv.z, bv.w);   // hi . lo   (x2048)
            }
            const int   jl = ob * 8 + 2 * t_;
            const float s0 = sqj[jl], s1 = sqj[jl + 1];
            const float d00 = s0 - 2.f * (ch[0] + (cl[0] + cl2[0]) * LOINV);
            const float d01 = s1 - 2.f * (ch[1] + (cl[1] + cl2[1]) * LOINV);
            const float d10 = s0 - 2.f * (ch[2] + (cl[2] + cl2[2]) * LOINV);
            const float d11 = s1 - 2.f * (ch[3] + (cl[3] + cl2[3]) * LOINV);
            const int jg = jbase + jl;
            if (d00 < dmax0 && jg     != ig0) topk_insert(td0, ti0, dmax0, mp0, d00, jg);
            if (d01 < dmax0 && jg + 1 != ig0) topk_insert(td0, ti0, dmax0, mp0, d01, jg + 1);
            if (d10 < dmax1 && jg     != ig1) topk_insert(td1, ti1, dmax1, mp1, d10, jg);
            if (d11 < dmax1 && jg + 1 != ig1) topk_insert(td1, ti1, dmax1, mp1, d11, jg + 1);
        }

        asm volatile("cp.async.wait_group 0;" ::: "memory");
        __syncthreads();
    }

    // ---- merge the 4 col-stripe lists per row (t_ == 0 does it) ----
    __syncthreads();
    if (t_ == 0) {
        #pragma unroll
        for (int s = 1; s < 4; s++) {
            const float* od0 = (const float*)(smem + SM_TD0) + (tid + s) * 17;
            const int*   oi0 = (const int*)  (smem + SM_TI0) + (tid + s) * 17;
            const float* od1 = (const float*)(smem + SM_TD1) + (tid + s) * 17;
            const int*   oi1 = (const int*)  (smem + SM_TI1) + (tid + s) * 17;
            #pragma unroll
            for (int p = 0; p < KNN; p++) {
                const float a = od0[p];
                if (a < dmax0) topk_insert(td0, ti0, dmax0, mp0, a, oi0[p]);
                const float c = od1[p];
                if (c < dmax1) topk_insert(td1, ti1, dmax1, mp1, c, oi1[p]);
            }
        }
        #pragma unroll
        for (int p = 0; p < KNN; p++) {
            g_idx[ig0 * KNN + p] = ti0[p];
            g_idx[ig1 * KNN + p] = ti1[p];
        }
    }
}

// ---------------------------------------------------------------------------
// Output: out[i] = relu(max_k (A_i + G_{idx[i,k]})), then (C,R)->(R,C) permute
// ---------------------------------------------------------------------------
__global__ __launch_bounds__(CR) void out_kernel(float* __restrict__ out) {
    __shared__ int   sidx[KNN];
    __shared__ float sv[CR];
    const int i = blockIdx.x;
    const int o = threadIdx.x;
    if (o < KNN) sidx[o] = g_idx[i * KNN + o];
    __syncthreads();

    const float a = g_A[i * CR + o];
    float m = -CUDART_INF_F;
    #pragma unroll
    for (int k = 0; k < KNN; k++) {
        m = fmaxf(m, a + g_G[sidx[k] * CR + o]);
    }
    sv[o] = fmaxf(m, 0.f);
    __syncthreads();

    const int p = o;
    const int r = p >> 6;
    const int c = p & 63;
    out[i * CR + p] = sv[c * Rr + r];
}

// ---------------------------------------------------------------------------
extern "C" void kernel_launch(void* const* d_in, const int* in_sizes, int n_in,
                              void* d_out, int out_size) {
    const float* x = (const float*)d_in[0];
    const float* W = (const float*)d_in[1];
    const float* b = (const float*)d_in[2];
    float* out = (float*)d_out;

    cudaFuncSetAttribute(knn_f16_kernel,
                         cudaFuncAttributeMaxDynamicSharedMemorySize, SM_TOT);

    xf_kernel<<<Nn * 16 / 256, 256>>>(x);
    ag_kernel<<<Nn / RI, 256>>>(x, W, b);
    knn_f16_kernel<<<Nn / IB, 256, SM_TOT>>>();
    out_kernel<<<Nn, CR>>>(out);
}

// round 9
// speedup vs baseline: 2.0550x; 1.0137x over previous
#include <cuda_runtime.h>
#include <cuda_fp16.h>
#include <math_constants.h>
#include <cstdint>

#define Nn   16384
#define Cc   64
#define KNN  16
#define Rr   4
#define CR   256              // C*R
#define RI   8                // rows per ag block
#define IB   128              // i-rows per knn CTA
#define TJ   128              // j-tile
#define NT   (Nn / TJ)        // 128 tiles
#define CAND 64               // candidates per row (4 stripes x 16)

// ---- scratch (device globals; no allocation allowed) ----
__device__ float g_A[Nn * CR];       // x @ (W1 - W2) + b
__device__ float g_G[Nn * CR];       // x @ W2
__device__ float g_sq[Nn];           // row squared norms
__device__ uint2 g_xh[Nn * 16];      // fp16 hi fragment-packed (2 MB)
__device__ int   g_ci[Nn * CAND];    // candidate indices (4 MB)
__device__ int   g_idx[Nn * KNN];    // final knn indices

// ---- smem map (bytes) for pass-1 knn kernel ----
#define SM_B    0                         // 2 x 2048 uint2 = 32768
#define SM_SQJ  32768                     // 2 x 128 floats = 1024
#define SM_TD0  33792                     // 256*17 floats
#define SM_TI0  51200
#define SM_TD1  68608
#define SM_TI1  86016
#define SM_TOT  103424

__device__ __forceinline__ uint32_t smem_u32(const void* p) {
    uint32_t a;
    asm("{ .reg .u64 t; cvta.to.shared.u64 t, %1; cvt.u32.u64 %0, t; }" : "=r"(a) : "l"(p));
    return a;
}

__device__ __forceinline__ void mma_f16(float* c, const uint32_t* a,
                                        uint32_t b0, uint32_t b1) {
    asm volatile(
        "mma.sync.aligned.m16n8k16.row.col.f32.f16.f16.f32 "
        "{%0,%1,%2,%3}, {%4,%5,%6,%7}, {%8,%9}, {%0,%1,%2,%3};"
        : "+f"(c[0]), "+f"(c[1]), "+f"(c[2]), "+f"(c[3])
        : "r"(a[0]), "r"(a[1]), "r"(a[2]), "r"(a[3]), "r"(b0), "r"(b1));
}

__device__ __forceinline__ void cpa16(uint32_t dst, const void* src) {
    asm volatile("cp.async.cg.shared.global [%0], [%1], 16;"
                 :: "r"(dst), "l"(__cvta_generic_to_global(src)));
}
__device__ __forceinline__ void cpa4(uint32_t dst, const void* src) {
    asm volatile("cp.async.ca.shared.global [%0], [%1], 4;"
                 :: "r"(dst), "l"(__cvta_generic_to_global(src)));
}

__device__ __forceinline__ uint32_t pack_h2(float a, float b) {  // a in low half
    __half2 h = __floats2half2_rn(a, b);
    return reinterpret_cast<uint32_t&>(h);
}

// ---------------------------------------------------------------------------
// Fragment pack (mapping validated R5/R8): slot s -> octet o = s>>7,
// q = (s>>5)&3, lane = s&31 (g = lane>>2, t = lane&3); row j = o*8+g,
// cols c = q*16 + 2t (+1, +8, +9).
// uint2 = (w0hi, w1hi): w0 = cols (2t,2t+1), w1 = cols (2t+8,2t+9).
// Serves as both A-row and B-col fragments of m16n8k16.row.col.
// ---------------------------------------------------------------------------
__global__ __launch_bounds__(256) void xf_kernel(const float* __restrict__ x) {
    const int s    = blockIdx.x * 256 + threadIdx.x;  // < Nn*16
    const int lane = s & 31;
    const int q    = (s >> 5) & 3;
    const int o    = s >> 7;
    const int g = lane >> 2, t = lane & 3;
    const int j = o * 8 + g;
    const int c = q * 16 + 2 * t;

    const float v0 = x[j * Cc + c];
    const float v1 = x[j * Cc + c + 1];
    const float v2 = x[j * Cc + c + 8];
    const float v3 = x[j * Cc + c + 9];

    uint2 out;
    out.x = pack_h2(v0, v1);
    out.y = pack_h2(v2, v3);
    g_xh[s] = out;
}

// ---------------------------------------------------------------------------
// A/G/sq precompute: block = 8 rows, 256 threads
// ---------------------------------------------------------------------------
__global__ __launch_bounds__(256) void ag_kernel(const float* __restrict__ x,
                                                 const float* __restrict__ W,
                                                 const float* __restrict__ b) {
    __shared__ float shx[RI * Cc];
    const int i0  = blockIdx.x * RI;
    const int tid = threadIdx.x;

    shx[tid]       = x[i0 * Cc + tid];
    shx[tid + 256] = x[i0 * Cc + tid + 256];
    __syncthreads();

    if (tid < RI) {
        float s = 0.f;
        #pragma unroll
        for (int c = 0; c < Cc; c++) { float v = shx[tid * Cc + c]; s = fmaf(v, v, s); }
        g_sq[i0 + tid] = s;
    }

    float aacc[RI], gacc[RI];
    const float bb = b[tid];
    #pragma unroll
    for (int r = 0; r < RI; r++) { aacc[r] = bb; gacc[r] = 0.f; }

    #pragma unroll 4
    for (int c = 0; c < Cc; c++) {
        const float w1 = W[c * CR + tid];
        const float w2 = W[(c + Cc) * CR + tid];
        const float wd = w1 - w2;
        #pragma unroll
        for (int r = 0; r < RI; r++) {
            const float xv = shx[r * Cc + c];
            aacc[r] = fmaf(xv, wd, aacc[r]);
            gacc[r] = fmaf(xv, w2, gacc[r]);
        }
    }
    #pragma unroll
    for (int r = 0; r < RI; r++) {
        g_A[(i0 + r) * CR + tid] = aacc[r];
        g_G[(i0 + r) * CR + tid] = gacc[r];
    }
}

// ---------------------------------------------------------------------------
// Streaming top-16 insert (per-thread smem lists, stride 17 = conflict-free)
// ---------------------------------------------------------------------------
__device__ __forceinline__ void topk_insert(float* td, int* ti,
                                            float& dmax, int& mp,
                                            float d, int j) {
    td[mp] = d; ti[mp] = j;
    float m = -CUDART_INF_F; int q = 0;
    #pragma unroll
    for (int p = 0; p < KNN; p++) {
        const float v = td[p];
        if (v > m) { m = v; q = p; }
    }
    dmax = m; mp = q;
}

// ---------------------------------------------------------------------------
// Pass 1: approximate KNN via fp16 hi.hi mma.sync, streaming stripe top-16.
// CTA = 128 i-rows (8 warps x 16 rows), tiles of 128 j, double-buffered B.
// Thread (g,t) of warp w: rows (w*16+g, +8); stripe t covers cols j%8 in
// {2t, 2t+1} per n-octet (disjoint j classes -> disjoint candidate lists).
// ---------------------------------------------------------------------------
__global__ __launch_bounds__(256, 1) void knn_pass1_kernel() {
    extern __shared__ char smem[];
    const uint32_t sb  = smem_u32(smem);
    const uint2* sB    = (const uint2*)smem;             // [2][2048]
    const float* sqjs  = (const float*)(smem + SM_SQJ);  // [2][128]

    const int tid  = threadIdx.x;
    const int w    = tid >> 5;
    const int lane = tid & 31;
    const int g_   = lane >> 2;
    const int t_   = lane & 3;
    const int bid  = blockIdx.x;
    const int i0   = bid * IB;
    const int ig0  = i0 + w * 16 + g_;
    const int ig1  = ig0 + 8;

    // ---- A fragments (hi only): rows i0 + w*16 .. +15 = octets oA, oA+1 ----
    uint32_t Ah[16];   // [q][4]
    {
        const int oA = bid * 16 + w * 2;
        #pragma unroll
        for (int q = 0; q < 4; q++) {
            const uint2 ua = g_xh[(oA * 4 + q) * 32 + lane];
            const uint2 ub = g_xh[((oA + 1) * 4 + q) * 32 + lane];
            Ah[q * 4 + 0] = ua.x; Ah[q * 4 + 1] = ub.x;
            Ah[q * 4 + 2] = ua.y; Ah[q * 4 + 3] = ub.y;
        }
    }

    // ---- per-thread top-16 lists (row g_, row g_+8) ----
    float* td0 = (float*)(smem + SM_TD0) + tid * 17;
    int*   ti0 = (int*)  (smem + SM_TI0) + tid * 17;
    float* td1 = (float*)(smem + SM_TD1) + tid * 17;
    int*   ti1 = (int*)  (smem + SM_TI1) + tid * 17;
    #pragma unroll
    for (int p = 0; p < KNN; p++) {
        td0[p] = CUDART_INF_F; ti0[p] = -1;
        td1[p] = CUDART_INF_F; ti1[p] = -1;
    }
    float dmax0 = CUDART_INF_F, dmax1 = CUDART_INF_F;
    int   mp0 = 0, mp1 = 0;

    // ---- tile fill: 2048 uint2 (16 KB) + 128 sq ----
    auto fill = [&](int jt, int buf) {
        const uint32_t dstB = sb + SM_B + buf * 16384 + tid * 16;
        const uint4* src = (const uint4*)(g_xh + (size_t)jt * 2048) + tid;
        #pragma unroll
        for (int s = 0; s < 4; s++) cpa16(dstB + s * 4096, src + s * 256);
        if (tid < TJ) cpa4(sb + SM_SQJ + buf * 512 + tid * 4, &g_sq[jt * TJ + tid]);
    };

    fill(0, 0);
    asm volatile("cp.async.commit_group;" ::: "memory");
    asm volatile("cp.async.wait_group 0;" ::: "memory");
    __syncthreads();

    for (int tt = 0; tt < NT; tt++) {
        const int buf = tt & 1;
        if (tt + 1 < NT) {
            fill(tt + 1, buf ^ 1);
            asm volatile("cp.async.commit_group;" ::: "memory");
        }
        const uint2* Bb  = sB + buf * 2048;
        const float* sqj = sqjs + buf * TJ;
        const int jbase  = tt * TJ;

        #pragma unroll 4
        for (int ob = 0; ob < 16; ob++) {
            float ch[4] = {0.f, 0.f, 0.f, 0.f};
            #pragma unroll
            for (int q = 0; q < 4; q++) {
                const uint2 bv = Bb[(ob * 4 + q) * 32 + lane];
                mma_f16(ch, Ah + q * 4, bv.x, bv.y);   // hi . hi
            }
            const int   jl = ob * 8 + 2 * t_;
            const float d00 = sqj[jl]     - 2.f * ch[0];   // row g_,   col jl
            const float d01 = sqj[jl + 1] - 2.f * ch[1];   // row g_,   col jl+1
            const float d10 = sqj[jl]     - 2.f * ch[2];   // row g_+8, col jl
            const float d11 = sqj[jl + 1] - 2.f * ch[3];   // row g_+8, col jl+1
            const int jg = jbase + jl;
            if (d00 < dmax0 && jg     != ig0) topk_insert(td0, ti0, dmax0, mp0, d00, jg);
            if (d01 < dmax0 && jg + 1 != ig0) topk_insert(td0, ti0, dmax0, mp0, d01, jg + 1);
            if (d10 < dmax1 && jg     != ig1) topk_insert(td1, ti1, dmax1, mp1, d10, jg);
            if (d11 < dmax1 && jg + 1 != ig1) topk_insert(td1, ti1, dmax1, mp1, d11, jg + 1);
        }

        asm volatile("cp.async.wait_group 0;" ::: "memory");
        __syncthreads();
    }

    // ---- write stripe candidate lists directly (no merge) ----
    #pragma unroll
    for (int p = 0; p < KNN; p++) {
        g_ci[ig0 * CAND + t_ * KNN + p] = ti0[p];
        g_ci[ig1 * CAND + t_ * KNN + p] = ti1[p];
    }
}

// ---------------------------------------------------------------------------
// Pass 2: exact fp32 refine of 64 candidates per row; warp per row.
// d(j) = sq_j - 2 * <x_i, x_j>  (sq_i constant per row, dropped).
// 16 rounds of warp argmin -> final knn indices.
// ---------------------------------------------------------------------------
__global__ __launch_bounds__(256) void refine_kernel(const float* __restrict__ x) {
    __shared__ float sxi[8 * Cc];
    const int tid  = threadIdx.x;
    const int w    = tid >> 5;
    const int lane = tid & 31;
    const int i    = blockIdx.x * 8 + w;

    ((float2*)sxi)[tid] = ((const float2*)(x + (size_t)blockIdx.x * 8 * Cc))[tid];
    __syncthreads();
    const float* xi = sxi + w * Cc;

    const int c0 = g_ci[i * CAND + lane];
    const int c1 = g_ci[i * CAND + 32 + lane];

    const float4* __restrict__ x4 = (const float4*)x;
    float dot0 = 0.f, dot1 = 0.f;
    #pragma unroll
    for (int c4 = 0; c4 < 16; c4++) {
        const float4 a = x4[c0 * 16 + c4];
        const float4 b = x4[c1 * 16 + c4];
        const float x0 = xi[c4 * 4 + 0], x1 = xi[c4 * 4 + 1];
        const float x2 = xi[c4 * 4 + 2], x3 = xi[c4 * 4 + 3];
        dot0 = fmaf(x0, a.x, dot0); dot0 = fmaf(x1, a.y, dot0);
        dot0 = fmaf(x2, a.z, dot0); dot0 = fmaf(x3, a.w, dot0);
        dot1 = fmaf(x0, b.x, dot1); dot1 = fmaf(x1, b.y, dot1);
        dot1 = fmaf(x2, b.z, dot1); dot1 = fmaf(x3, b.w, dot1);
    }
    float d0 = g_sq[c0] - 2.f * dot0;
    float d1 = g_sq[c1] - 2.f * dot1;

    #pragma unroll
    for (int r = 0; r < KNN; r++) {
        float bd; int bj;
        if (d0 <= d1) { bd = d0; bj = c0; } else { bd = d1; bj = c1; }
        #pragma unroll
        for (int s = 16; s; s >>= 1) {
            const float od = __shfl_xor_sync(0xFFFFFFFFu, bd, s);
            const int   oj = __shfl_xor_sync(0xFFFFFFFFu, bj, s);
            if (od < bd || (od == bd && oj < bj)) { bd = od; bj = oj; }
        }
        if (lane == 0) g_idx[i * KNN + r] = bj;
        if (c0 == bj) d0 = CUDART_INF_F;
        if (c1 == bj) d1 = CUDART_INF_F;
    }
}

// ---------------------------------------------------------------------------
// Output: out[i] = relu(max_k (A_i + G_{idx[i,k]})), then (C,R)->(R,C) permute
// ---------------------------------------------------------------------------
__global__ __launch_bounds__(CR) void out_kernel(float* __restrict__ out) {
    __shared__ int   sidx[KNN];
    __shared__ float sv[CR];
    const int i = blockIdx.x;
    const int o = threadIdx.x;
    if (o < KNN) sidx[o] = g_idx[i * KNN + o];
    __syncthreads();

    const float a = g_A[i * CR + o];
    float m = -CUDART_INF_F;
    #pragma unroll
    for (int k = 0; k < KNN; k++) {
        m = fmaxf(m, a + g_G[sidx[k] * CR + o]);
    }
    sv[o] = fmaxf(m, 0.f);
    __syncthreads();

    const int p = o;
    const int r = p >> 6;
    const int c = p & 63;
    out[i * CR + p] = sv[c * Rr + r];
}

// ---------------------------------------------------------------------------
extern "C" void kernel_launch(void* const* d_in, const int* in_sizes, int n_in,
                              void* d_out, int out_size) {
    const float* x = (const float*)d_in[0];
    const float* W = (const float*)d_in[1];
    const float* b = (const float*)d_in[2];
    float* out = (float*)d_out;

    cudaFuncSetAttribute(knn_pass1_kernel,
                         cudaFuncAttributeMaxDynamicSharedMemorySize, SM_TOT);

    xf_kernel<<<Nn * 16 / 256, 256>>>(x);
    ag_kernel<<<Nn / RI, 256>>>(x, W, b);
    knn_pass1_kernel<<<Nn / IB, 256, SM_TOT>>>();
    refine_kernel<<<Nn / 8, 256>>>(x);
    out_kernel<<<Nn, CR>>>(out);
}

// round 13
// speedup vs baseline: 2.4927x; 1.2130x over previous
#include <cuda_runtime.h>
#include <cuda_fp16.h>
#include <math_constants.h>
#include <cstdint>

#define Nn   16384
#define Cc   64
#define KNN  16
#define Rr   4
#define CR   256              // C*R
#define RI   8                // rows per ag block
#define IB   64               // i-rows per knn CTA
#define TJ   128              // j-tile
#define NT   (Nn / TJ)        // 128 tiles
#define CAND 64               // candidates per row (4 stripes x 16)

// ---- scratch (device globals; no allocation allowed) ----
__device__ float g_A[Nn * CR];       // x @ (W1 - W2) + b
__device__ float g_G[Nn * CR];       // x @ W2
__device__ float g_sq[Nn];           // row squared norms
__device__ uint2 g_xh[Nn * 16];      // fp16 hi fragment-packed (2 MB)
__device__ int   g_ci[Nn * CAND];    // candidate indices (4 MB)
__device__ int   g_idx[Nn * KNN];    // final knn indices

// ---- smem map (bytes) for pass-1 knn kernel ----
#define SM_B    0                         // 2 x 2048 uint2 = 32768
#define SM_SQJ  32768                     // 2 x 128 floats = 1024
#define SM_TOT  33792

__device__ __forceinline__ uint32_t smem_u32(const void* p) {
    uint32_t a;
    asm("{ .reg .u64 t; cvta.to.shared.u64 t, %1; cvt.u32.u64 %0, t; }" : "=r"(a) : "l"(p));
    return a;
}

__device__ __forceinline__ void mma_f16(float* c, const uint32_t* a,
                                        uint32_t b0, uint32_t b1) {
    asm volatile(
        "mma.sync.aligned.m16n8k16.row.col.f32.f16.f16.f32 "
        "{%0,%1,%2,%3}, {%4,%5,%6,%7}, {%8,%9}, {%0,%1,%2,%3};"
        : "+f"(c[0]), "+f"(c[1]), "+f"(c[2]), "+f"(c[3])
        : "r"(a[0]), "r"(a[1]), "r"(a[2]), "r"(a[3]), "r"(b0), "r"(b1));
}

__device__ __forceinline__ void cpa16(uint32_t dst, const void* src) {
    asm volatile("cp.async.cg.shared.global [%0], [%1], 16;"
                 :: "r"(dst), "l"(__cvta_generic_to_global(src)));
}
__device__ __forceinline__ void cpa4(uint32_t dst, const void* src) {
    asm volatile("cp.async.ca.shared.global [%0], [%1], 4;"
                 :: "r"(dst), "l"(__cvta_generic_to_global(src)));
}

__device__ __forceinline__ uint32_t pack_h2(float a, float b) {  // a in low half
    __half2 h = __floats2half2_rn(a, b);
    return reinterpret_cast<uint32_t&>(h);
}

// Monotonic float->uint map (order-preserving incl. negatives), low 14 bits
// replaced by the j index: rank by quantized distance, tie-break by j.
__device__ __forceinline__ uint32_t dkey(float d, int j) {
    uint32_t u = __float_as_uint(d);
    u ^= (uint32_t)((int)u >> 31) | 0x80000000u;
    return (u & 0xFFFFC000u) | (uint32_t)j;
}

// Bubble-pass insert: list <- 16 smallest of (list ∪ {key}); carry-out = evicted
// max, reused as a conservative (self-tightening) guard threshold.
__device__ __forceinline__ void kins(uint32_t (&kl)[16], uint32_t& kmax, uint32_t key) {
    uint32_t c = key;
    #pragma unroll
    for (int p = 0; p < KNN; p++) {
        const uint32_t lo = min(c, kl[p]);
        c = max(c, kl[p]);
        kl[p] = lo;
    }
    kmax = c;
}

// ---------------------------------------------------------------------------
// Fragment pack (mapping validated R5/R8/R9): slot s -> octet o = s>>7,
// q = (s>>5)&3, lane = s&31 (g = lane>>2, t = lane&3); row j = o*8+g,
// cols c = q*16 + 2t (+1, +8, +9). uint2 = (w0hi, w1hi).
// Serves as both A-row and B-col fragments of m16n8k16.row.col.
// ---------------------------------------------------------------------------
__global__ __launch_bounds__(256) void xf_kernel(const float* __restrict__ x) {
    const int s    = blockIdx.x * 256 + threadIdx.x;  // < Nn*16
    const int lane = s & 31;
    const int q    = (s >> 5) & 3;
    const int o    = s >> 7;
    const int g = lane >> 2, t = lane & 3;
    const int j = o * 8 + g;
    const int c = q * 16 + 2 * t;

    const float v0 = x[j * Cc + c];
    const float v1 = x[j * Cc + c + 1];
    const float v2 = x[j * Cc + c + 8];
    const float v3 = x[j * Cc + c + 9];

    uint2 out;
    out.x = pack_h2(v0, v1);
    out.y = pack_h2(v2, v3);
    g_xh[s] = out;
}

// ---------------------------------------------------------------------------
// A/G/sq precompute: block = 8 rows, 256 threads
// ---------------------------------------------------------------------------
__global__ __launch_bounds__(256) void ag_kernel(const float* __restrict__ x,
                                                 const float* __restrict__ W,
                                                 const float* __restrict__ b) {
    __shared__ float shx[RI * Cc];
    const int i0  = blockIdx.x * RI;
    const int tid = threadIdx.x;

    shx[tid]       = x[i0 * Cc + tid];
    shx[tid + 256] = x[i0 * Cc + tid + 256];
    __syncthreads();

    if (tid < RI) {
        float s = 0.f;
        #pragma unroll
        for (int c = 0; c < Cc; c++) { float v = shx[tid * Cc + c]; s = fmaf(v, v, s); }
        g_sq[i0 + tid] = s;
    }

    float aacc[RI], gacc[RI];
    const float bb = b[tid];
    #pragma unroll
    for (int r = 0; r < RI; r++) { aacc[r] = bb; gacc[r] = 0.f; }

    #pragma unroll 4
    for (int c = 0; c < Cc; c++) {
        const float w1 = W[c * CR + tid];
        const float w2 = W[(c + Cc) * CR + tid];
        const float wd = w1 - w2;
        #pragma unroll
        for (int r = 0; r < RI; r++) {
            const float xv = shx[r * Cc + c];
            aacc[r] = fmaf(xv, wd, aacc[r]);
            gacc[r] = fmaf(xv, w2, gacc[r]);
        }
    }
    #pragma unroll
    for (int r = 0; r < RI; r++) {
        g_A[(i0 + r) * CR + tid] = aacc[r];
        g_G[(i0 + r) * CR + tid] = gacc[r];
    }
}

// ---------------------------------------------------------------------------
// Pass 1: approximate KNN, fp16 hi.hi mma.sync, packed-key register top-16.
// CTA = 64 i-rows (4 warps x 16), 128 threads, grid 256, tiles of 128 j,
// double-buffered cp.async B. Thread (g,t) of warp w: rows (w*16+g, +8);
// stripe t covers j%8 in {2t, 2t+1}. Self-match NOT filtered (refine does).
// ---------------------------------------------------------------------------
__global__ __launch_bounds__(128, 2) void knn_pass1_kernel() {
    extern __shared__ char smem[];
    const uint32_t sb  = smem_u32(smem);
    const uint2* sB    = (const uint2*)smem;             // [2][2048]
    const float* sqjs  = (const float*)(smem + SM_SQJ);  // [2][128]

    const int tid  = threadIdx.x;
    const int w    = tid >> 5;
    const int lane = tid & 31;
    const int g_   = lane >> 2;
    const int t_   = lane & 3;
    const int bid  = blockIdx.x;
    const int i0   = bid * IB;
    const int ig0  = i0 + w * 16 + g_;
    const int ig1  = ig0 + 8;

    // ---- A fragments (hi only): rows i0 + w*16 .. +15 = octets oA, oA+1 ----
    uint32_t Ah[16];   // [q][4]
    {
        const int oA = bid * 8 + w * 2;
        #pragma unroll
        for (int q = 0; q < 4; q++) {
            const uint2 ua = g_xh[(oA * 4 + q) * 32 + lane];
            const uint2 ub = g_xh[((oA + 1) * 4 + q) * 32 + lane];
            Ah[q * 4 + 0] = ua.x; Ah[q * 4 + 1] = ub.x;
            Ah[q * 4 + 2] = ua.y; Ah[q * 4 + 3] = ub.y;
        }
    }

    // ---- packed-key top-16 lists in registers ----
    uint32_t kl0[16], kl1[16];
    #pragma unroll
    for (int p = 0; p < KNN; p++) { kl0[p] = 0xFFFFFFFFu; kl1[p] = 0xFFFFFFFFu; }
    uint32_t kmax0 = 0xFFFFFFFFu, kmax1 = 0xFFFFFFFFu;

    // ---- tile fill: 2048 uint2 (16 KB) + 128 sq ----
    auto fill = [&](int jt, int buf) {
        const uint32_t dstB = sb + SM_B + buf * 16384 + tid * 16;
        const uint4* src = (const uint4*)(g_xh + (size_t)jt * 2048) + tid;
        #pragma unroll
        for (int s = 0; s < 8; s++) cpa16(dstB + s * 2048, src + s * 128);
        cpa4(sb + SM_SQJ + buf * 512 + tid * 4, &g_sq[jt * TJ + tid]);
    };

    fill(0, 0);
    asm volatile("cp.async.commit_group;" ::: "memory");
    asm volatile("cp.async.wait_group 0;" ::: "memory");
    __syncthreads();

    for (int tt = 0; tt < NT; tt++) {
        const int buf = tt & 1;
        if (tt + 1 < NT) {
            fill(tt + 1, buf ^ 1);
            asm volatile("cp.async.commit_group;" ::: "memory");
        }
        const uint2* Bb  = sB + buf * 2048;
        const float* sqj = sqjs + buf * TJ;
        const int jbase  = tt * TJ;

        #pragma unroll 4
        for (int ob = 0; ob < 16; ob++) {
            float ch[4] = {0.f, 0.f, 0.f, 0.f};
            #pragma unroll
            for (int q = 0; q < 4; q++) {
                const uint2 bv = Bb[(ob * 4 + q) * 32 + lane];
                mma_f16(ch, Ah + q * 4, bv.x, bv.y);   // hi . hi
            }
            const int jl = ob * 8 + 2 * t_;
            const int jg = jbase + jl;
            const float s0 = sqj[jl], s1 = sqj[jl + 1];
            const uint32_t k00 = dkey(s0 - 2.f * ch[0], jg);      // row g_,   col jl
            const uint32_t k01 = dkey(s1 - 2.f * ch[1], jg + 1);  // row g_,   col jl+1
            const uint32_t k10 = dkey(s0 - 2.f * ch[2], jg);      // row g_+8, col jl
            const uint32_t k11 = dkey(s1 - 2.f * ch[3], jg + 1);  // row g_+8, col jl+1
            if (k00 < kmax0) kins(kl0, kmax0, k00);
            if (k01 < kmax0) kins(kl0, kmax0, k01);
            if (k10 < kmax1) kins(kl1, kmax1, k10);
            if (k11 < kmax1) kins(kl1, kmax1, k11);
        }

        asm volatile("cp.async.wait_group 0;" ::: "memory");
        __syncthreads();
    }

    // ---- write stripe candidate indices (low 14 bits of keys) ----
    #pragma unroll
    for (int p = 0; p < KNN; p++) {
        g_ci[ig0 * CAND + t_ * KNN + p] = (int)(kl0[p] & 0x3FFFu);
        g_ci[ig1 * CAND + t_ * KNN + p] = (int)(kl1[p] & 0x3FFFu);
    }
}

// ---------------------------------------------------------------------------
// Pass 2: exact fp32 refine of 64 candidates per row; warp per row.
// d(j) = sq_j - 2 * <x_i, x_j>; self (j == i) excluded here.
// 16 rounds of warp argmin -> final knn indices.
// ---------------------------------------------------------------------------
__global__ __launch_bounds__(256) void refine_kernel(const float* __restrict__ x) {
    __shared__ float sxi[8 * Cc];
    const int tid  = threadIdx.x;
    const int w    = tid >> 5;
    const int lane = tid & 31;
    const int i    = blockIdx.x * 8 + w;

    ((float2*)sxi)[tid] = ((const float2*)(x + (size_t)blockIdx.x * 8 * Cc))[tid];
    __syncthreads();
    const float* xi = sxi + w * Cc;

    const int c0 = g_ci[i * CAND + lane];
    const int c1 = g_ci[i * CAND + 32 + lane];

    const float4* __restrict__ x4 = (const float4*)x;
    float dot0 = 0.f, dot1 = 0.f;
    #pragma unroll
    for (int c4 = 0; c4 < 16; c4++) {
        const float4 a = x4[c0 * 16 + c4];
        const float4 b = x4[c1 * 16 + c4];
        const float x0 = xi[c4 * 4 + 0], x1 = xi[c4 * 4 + 1];
        const float x2 = xi[c4 * 4 + 2], x3 = xi[c4 * 4 + 3];
        dot0 = fmaf(x0, a.x, dot0); dot0 = fmaf(x1, a.y, dot0);
        dot0 = fmaf(x2, a.z, dot0); dot0 = fmaf(x3, a.w, dot0);
        dot1 = fmaf(x0, b.x, dot1); dot1 = fmaf(x1, b.y, dot1);
        dot1 = fmaf(x2, b.z, dot1); dot1 = fmaf(x3, b.w, dot1);
    }
    float d0 = g_sq[c0] - 2.f * dot0;
    float d1 = g_sq[c1] - 2.f * dot1;
    if (c0 == i) d0 = CUDART_INF_F;
    if (c1 == i) d1 = CUDART_INF_F;

    #pragma unroll
    for (int r = 0; r < KNN; r++) {
        float bd; int bj;
        if (d0 <= d1) { bd = d0; bj = c0; } else { bd = d1; bj = c1; }
        #pragma unroll
        for (int s = 16; s; s >>= 1) {
            const float od = __shfl_xor_sync(0xFFFFFFFFu, bd, s);
            const int   oj = __shfl_xor_sync(0xFFFFFFFFu, bj, s);
            if (od < bd || (od == bd && oj < bj)) { bd = od; bj = oj; }
        }
        if (lane == 0) g_idx[i * KNN + r] = bj;
        if (c0 == bj) d0 = CUDART_INF_F;
        if (c1 == bj) d1 = CUDART_INF_F;
    }
}

// ---------------------------------------------------------------------------
// Output: out[i] = relu(max_k (A_i + G_{idx[i,k]})), then (C,R)->(R,C) permute
// ---------------------------------------------------------------------------
__global__ __launch_bounds__(CR) void out_kernel(float* __restrict__ out) {
    __shared__ int   sidx[KNN];
    __shared__ float sv[CR];
    const int i = blockIdx.x;
    const int o = threadIdx.x;
    if (o < KNN) sidx[o] = g_idx[i * KNN + o];
    __syncthreads();

    const float a = g_A[i * CR + o];
    float m = -CUDART_INF_F;
    #pragma unroll
    for (int k = 0; k < KNN; k++) {
        m = fmaxf(m, a + g_G[sidx[k] * CR + o]);
    }
    sv[o] = fmaxf(m, 0.f);
    __syncthreads();

    const int p = o;
    const int r = p >> 6;
    const int c = p & 63;
    out[i * CR + p] = sv[c * Rr + r];
}

// ---------------------------------------------------------------------------
extern "C" void kernel_launch(void* const* d_in, const int* in_sizes, int n_in,
                              void* d_out, int out_size) {
    const float* x = (const float*)d_in[0];
    const float* W = (const float*)d_in[1];
    const float* b = (const float*)d_in[2];
    float* out = (float*)d_out;

    xf_kernel<<<Nn * 16 / 256, 256>>>(x);
    ag_kernel<<<Nn / RI, 256>>>(x, W, b);
    knn_pass1_kernel<<<Nn / IB, 128, SM_TOT>>>();
    refine_kernel<<<Nn / 8, 256>>>(x);
    out_kernel<<<Nn, CR>>>(out);
}